// round 1
// baseline (speedup 1.0000x reference)
#include <cuda_runtime.h>
#include <cuda_bf16.h>

// Problem constants
#define BQ   256   // batch
#define TT   512   // seq len
#define EE   128   // embed dim
#define HH   256   // hidden
#define H3   768   // 3*H
#define NB   4     // batch elems per CTA
#define NTH  384   // threads per GRU CTA (12 warps, 3/SMSP)

typedef unsigned long long u64;

// ---------------- device scratch (no allocations allowed) ----------------
__device__ float4 g_wT4[(2 * 384 * H3) / 4];   // transposed [dir][k(0..383)][j(0..767)]
__device__ float  g_fc1T[512 * 128];           // fc1_w transposed [k][i]
__device__ float  g_fc2T[128 * 64];            // fc2_w transposed [k][o]
__device__ float  g_h[BQ * 2 * HH];            // concat(hf, hb) per batch row
__device__ int    g_order[BQ];                 // batch indices sorted by length

// ---------------- f32x2 helpers ----------------
__device__ __forceinline__ u64 ffma2(u64 a, u64 b, u64 c) {
    u64 d;
    asm("fma.rn.f32x2 %0, %1, %2, %3;" : "=l"(d) : "l"(a), "l"(b), "l"(c));
    return d;
}
__device__ __forceinline__ u64 pack2(float lo, float hi) {
    u64 d;
    asm("mov.b64 %0, {%1, %2};" : "=l"(d) : "f"(lo), "f"(hi));
    return d;
}
__device__ __forceinline__ void unpack2(u64 v, float& lo, float& hi) {
    asm("mov.b64 {%0, %1}, %2;" : "=f"(lo), "=f"(hi) : "l"(v));
}
__device__ __forceinline__ float lo_of(u64 v) { float a, b; unpack2(v, a, b); return a; }

__device__ __forceinline__ float sigf(float x) {
    return __fdividef(1.0f, 1.0f + __expf(-x));
}
__device__ __forceinline__ float tanhfast(float x) {
    return 1.0f - __fdividef(2.0f, __expf(2.0f * x) + 1.0f);
}

// ---------------- prep: transpose all weight matrices ----------------
__global__ void prep_kernel(const float* __restrict__ wihf, const float* __restrict__ whhf,
                            const float* __restrict__ wihb, const float* __restrict__ whhb,
                            const float* __restrict__ fc1w, const float* __restrict__ fc2w) {
    int idx = blockIdx.x * blockDim.x + threadIdx.x;
    float* wT = (float*)g_wT4;
    const int NW = 2 * 384 * H3;           // 589824
    if (idx < NW) {
        int dir = idx / (384 * H3);
        int r   = idx % (384 * H3);
        int k = r / H3, j = r % H3;
        const float* wih = dir ? wihb : wihf;
        const float* whh = dir ? whhb : whhf;
        wT[idx] = (k < 128) ? wih[j * EE + k] : whh[j * HH + (k - 128)];
    } else if (idx < NW + 512 * 128) {
        int o = idx - NW;
        int k = o / 128, i = o % 128;
        g_fc1T[o] = fc1w[i * 512 + k];
    } else if (idx < NW + 512 * 128 + 128 * 64) {
        int o = idx - (NW + 512 * 128);
        int k = o / 64, i = o % 64;
        g_fc2T[o] = fc2w[i * 128 + k];
    }
}

// ---------------- sort batch indices by length (bitonic, 1 CTA) ----------------
__global__ void sort_kernel(const int* __restrict__ lengths) {
    __shared__ int key[BQ], val[BQ];
    unsigned t = threadIdx.x;
    key[t] = lengths[t];
    val[t] = (int)t;
    __syncthreads();
    for (unsigned size = 2; size <= BQ; size <<= 1) {
        for (unsigned stride = size >> 1; stride > 0; stride >>= 1) {
            __syncthreads();
            unsigned j = t ^ stride;
            if (j > t) {
                bool up = ((t & size) == 0);
                int kt = key[t], kj = key[j];
                if ((kt > kj) == up) {
                    key[t] = kj; key[j] = kt;
                    int vt = val[t]; val[t] = val[j]; val[j] = vt;
                }
            }
        }
    }
    __syncthreads();
    g_order[t] = val[t];
}

// ---------------- GRU: persistent CTA per (group of 4 batch, direction) ----------------
__global__ __launch_bounds__(NTH, 1) void gru_kernel(
    const int* __restrict__ x, const int* __restrict__ lengths,
    const float* __restrict__ emb,
    const float* __restrict__ bih_f, const float* __restrict__ bhh_f,
    const float* __restrict__ bih_b, const float* __restrict__ bhh_b) {

    const int g = blockIdx.x, dir = blockIdx.y, tid = threadIdx.x;

    __shared__ __align__(16) u64 es[NB][EE];        // embedding, each entry {e,e} duplicated
    __shared__ __align__(16) u64 hs[2][NB][HH];     // hidden double-buffer, {h,h} duplicated
    __shared__ float z_s[NB][HH];
    __shared__ float xn_s[NB][HH];
    __shared__ float hn_s[NB][HH];
    __shared__ int ob_s[NB], len_s[NB];

    if (tid < NB) {
        int o = g_order[g * NB + tid];
        ob_s[tid] = o;
        len_s[tid] = lengths[o];
    }
    for (int i = tid; i < NB * HH; i += NTH) ((u64*)hs)[i] = 0ull;
    __syncthreads();

    const int M = max(max(len_s[0], len_s[1]), max(len_s[2], len_s[3]));
    const float* wb  = ((const float*)g_wT4) + dir * (384 * H3);
    const float* bih = dir ? bih_b : bih_f;
    const float* bhh = dir ? bhh_b : bhh_f;
    const int j2 = tid * 2;                 // this thread's output column pair

    // prologue: gather embedding for step 0
    if (tid >= 128 && tid < 256) {
        int t0 = dir ? (M - 1) : 0;
        int i = tid - 128, nb = i >> 5, ln = i & 31;
        int tok = x[ob_s[nb] * TT + t0];
        float4 v = *(const float4*)(emb + (size_t)tok * EE + ln * 4);
        u64* ep = &es[nb][ln * 4];
        ep[0] = pack2(v.x, v.x); ep[1] = pack2(v.y, v.y);
        ep[2] = pack2(v.z, v.z); ep[3] = pack2(v.w, v.w);
    }
    __syncthreads();

    const u64 bx = pack2(bih[j2], bih[j2 + 1]);
    const u64 bh = pack2(bhh[j2], bhh[j2 + 1]);
    int cur = 0;

    for (int s = 0; s < M; s++) {
        const int tcur = dir ? (M - 1 - s) : s;

        u64 xa[NB], ha[NB];
#pragma unroll
        for (int nb = 0; nb < NB; nb++) { xa[nb] = bx; ha[nb] = bh; }

        // input projection: k over E=128 (transposed weights, coalesced LDG)
#pragma unroll 4
        for (int k = 0; k < EE; k += 2) {
            u64 w0 = *(const u64*)(wb + (k) * H3 + j2);
            u64 w1 = *(const u64*)(wb + (k + 1) * H3 + j2);
#pragma unroll
            for (int nb = 0; nb < NB; nb++) {
                ulonglong2 ev = *(const ulonglong2*)&es[nb][k];
                xa[nb] = ffma2(w0, ev.x, xa[nb]);
                xa[nb] = ffma2(w1, ev.y, xa[nb]);
            }
        }
        // hidden projection: k over H=256
        const float* whh = wb + 128 * H3;
#pragma unroll 4
        for (int k = 0; k < HH; k += 2) {
            u64 w0 = *(const u64*)(whh + (k) * H3 + j2);
            u64 w1 = *(const u64*)(whh + (k + 1) * H3 + j2);
#pragma unroll
            for (int nb = 0; nb < NB; nb++) {
                ulonglong2 hv = *(const ulonglong2*)&hs[cur][nb][k];
                ha[nb] = ffma2(w0, hv.x, ha[nb]);
                ha[nb] = ffma2(w1, hv.y, ha[nb]);
            }
        }

        // gate stage A: publish z / (xn,hn); keep r local (phase-B threads ARE r threads)
        float rloc[NB][2];
        const int gate = tid >> 7;          // 0:r 1:z 2:n
        const int u2 = j2 & 255;
#pragma unroll
        for (int nb = 0; nb < NB; nb++) {
            float x0, x1, h0, h1;
            unpack2(xa[nb], x0, x1);
            unpack2(ha[nb], h0, h1);
            if (gate == 0) {
                rloc[nb][0] = sigf(x0 + h0);
                rloc[nb][1] = sigf(x1 + h1);
            } else if (gate == 1) {
                z_s[nb][u2] = sigf(x0 + h0);
                z_s[nb][u2 + 1] = sigf(x1 + h1);
            } else {
                xn_s[nb][u2] = x0; xn_s[nb][u2 + 1] = x1;
                hn_s[nb][u2] = h0; hn_s[nb][u2 + 1] = h1;
            }
        }
        __syncthreads();

        if (tid < 128) {
            // gate stage B: combine + ragged mask, write next hidden buffer
#pragma unroll
            for (int nb = 0; nb < NB; nb++) {
                bool upd = (tcur < len_s[nb]);
#pragma unroll
                for (int jj = 0; jj < 2; jj++) {
                    int u = j2 + jj;
                    float hold = lo_of(hs[cur][nb][u]);
                    float hnew = hold;
                    if (upd) {
                        float z = z_s[nb][u];
                        float n = tanhfast(xn_s[nb][u] + rloc[nb][jj] * hn_s[nb][u]);
                        hnew = (1.0f - z) * n + z * hold;
                    }
                    hs[cur ^ 1][nb][u] = pack2(hnew, hnew);
                }
            }
        } else if (tid < 256 && (s + 1) < M) {
            // overlap: gather embedding for next step
            int tn = dir ? (M - 2 - s) : (s + 1);
            int i = tid - 128, nb = i >> 5, ln = i & 31;
            int tok = x[ob_s[nb] * TT + tn];
            float4 v = *(const float4*)(emb + (size_t)tok * EE + ln * 4);
            u64* ep = &es[nb][ln * 4];
            ep[0] = pack2(v.x, v.x); ep[1] = pack2(v.y, v.y);
            ep[2] = pack2(v.z, v.z); ep[3] = pack2(v.w, v.w);
        }
        __syncthreads();
        cur ^= 1;
    }

    // write final hidden state: g_h[orig_b][dir*H + u]
    for (int i = tid; i < NB * HH; i += NTH) {
        int nb = i >> 8, u = i & 255;
        g_h[(size_t)ob_s[nb] * (2 * HH) + dir * HH + u] = lo_of(hs[cur][nb][u]);
    }
}

// ---------------- head: fc1 + relu + fc2 + L2 normalize ----------------
__global__ __launch_bounds__(128) void head_kernel(const float* __restrict__ fc1_b,
                                                   const float* __restrict__ fc2_b,
                                                   float* __restrict__ out) {
    __shared__ float hsm[512];
    __shared__ float hid[128];
    __shared__ float osm[64];
    __shared__ float inv_s;
    const int b = blockIdx.x, t = threadIdx.x;

    ((float4*)hsm)[t] = ((const float4*)(g_h + (size_t)b * 512))[t];
    __syncthreads();

    float acc = fc1_b[t];
#pragma unroll 8
    for (int k = 0; k < 512; k++) acc += g_fc1T[k * 128 + t] * hsm[k];
    hid[t] = fmaxf(acc, 0.0f);
    __syncthreads();

    if (t < 64) {
        float a = fc2_b[t];
#pragma unroll 8
        for (int k = 0; k < 128; k++) a += g_fc2T[k * 64 + t] * hid[k];
        osm[t] = a;
    }
    __syncthreads();
    if (t == 0) {
        float ss = 0.0f;
        for (int o = 0; o < 64; o++) ss += osm[o] * osm[o];
        float nrm = sqrtf(ss);
        inv_s = 1.0f / fmaxf(nrm, 1e-12f);
    }
    __syncthreads();
    if (t < 64) out[b * 64 + t] = osm[t] * inv_s;
}

// ---------------- launch ----------------
extern "C" void kernel_launch(void* const* d_in, const int* in_sizes, int n_in,
                              void* d_out, int out_size) {
    const int*   x        = (const int*)d_in[0];
    const int*   lengths  = (const int*)d_in[1];
    const float* emb      = (const float*)d_in[2];
    const float* w_ih_f   = (const float*)d_in[3];
    const float* w_hh_f   = (const float*)d_in[4];
    const float* b_ih_f   = (const float*)d_in[5];
    const float* b_hh_f   = (const float*)d_in[6];
    const float* w_ih_b   = (const float*)d_in[7];
    const float* w_hh_b   = (const float*)d_in[8];
    const float* b_ih_b   = (const float*)d_in[9];
    const float* b_hh_b   = (const float*)d_in[10];
    const float* fc1_w    = (const float*)d_in[11];
    const float* fc1_b    = (const float*)d_in[12];
    const float* fc2_w    = (const float*)d_in[13];
    const float* fc2_b    = (const float*)d_in[14];
    float* out = (float*)d_out;

    const int total = 2 * 384 * H3 + 512 * 128 + 128 * 64;  // 663552
    prep_kernel<<<(total + 255) / 256, 256>>>(w_ih_f, w_hh_f, w_ih_b, w_hh_b, fc1_w, fc2_w);
    sort_kernel<<<1, BQ>>>(lengths);
    dim3 gg(BQ / NB, 2);
    gru_kernel<<<gg, NTH>>>(x, lengths, emb, b_ih_f, b_hh_f, b_ih_b, b_hh_b);
    head_kernel<<<BQ, 128>>>(fc1_b, fc2_b, out);
}